// round 9
// baseline (speedup 1.0000x reference)
#include <cuda_runtime.h>
#include <cstdint>

#define N_INS 8192
#define T_MAX 16
#define HID   256
#define GATES 1024
#define NCLUS 8

// ---------------- scratch (static device globals; no allocations) ----------
__device__ float g_H[2 * N_INS * HID];    // ping-pong hidden state
__device__ float g_C[N_INS * HID];        // cell state
__device__ float g_G[N_INS * GATES];      // precomputed ins_embeds @ Wih_i^T
__device__ float g_part[NCLUS * N_INS];   // per-cluster-CTA output partials

// ---------------- packed f32x2 helpers ----------
#define FMA2(d, a, b) \
    asm("fma.rn.f32x2 %0, %1, %2, %0;" : "+l"(d) : "l"(a), "l"(b))
#define UNPACK2(lo, hi, v) \
    asm("mov.b64 {%0, %1}, %2;" : "=f"(lo), "=f"(hi) : "l"(v))

__device__ __forceinline__ float fsig(float x) {
    return __fdividef(1.0f, 1.0f + __expf(-x));
}
__device__ __forceinline__ float ftanh_(float x) {
    float e2 = __expf(2.0f * fminf(x, 30.0f));
    return __fdividef(e2 - 1.0f, e2 + 1.0f);
}

__device__ __forceinline__ void fma8(unsigned long long* acc, float a,
                                     const ulonglong2& w01, const ulonglong2& w23) {
    unsigned long long ap;
    asm("mov.b64 %0, {%1, %1};" : "=l"(ap) : "r"(__float_as_uint(a)));
    FMA2(acc[0], ap, w01.x);
    FMA2(acc[1], ap, w01.y);
    FMA2(acc[2], ap, w23.x);
    FMA2(acc[3], ap, w23.y);
}

// ---------------------------------------------------------------------------
// f32x2 GEMM, 128x128 tile, 256 threads, 8x8 micro-tile, smem double-buffered
// (one __syncthreads per k-tile; measured 210us).
// MODE 1: dual-source + fused token-LSTM epilogue (gate-interleaved cols).
// MODE 0: single source, plain C = A1 @ W1^T.
// ---------------------------------------------------------------------------
template<int MODE>
__global__ void __launch_bounds__(256)
gemm_k(float* __restrict__ Cmat,
       const float* __restrict__ A1, int lda1, const float* __restrict__ W1,
       const float* __restrict__ A2, const float* __restrict__ W2,
       const int* __restrict__ lengths,
       const float* __restrict__ bih, const float* __restrict__ bhh,
       const float* __restrict__ Hr, float* __restrict__ Hw,
       float* __restrict__ Cs, int t)
{
    __shared__ __align__(16) float As[2][16][132];
    __shared__ __align__(16) float Ws[2][16][132];

    const int tid = threadIdx.x;
    const int bm  = blockIdx.x * 128;
    const int bn  = blockIdx.y;
    const int tx  = tid & 15;
    const int ty  = tid >> 4;
    const int NT  = (MODE == 1) ? 32 : 16;

    const int lrow = tid >> 2;
    const int kq   = (tid & 3) << 2;

    int wr0, wr1;
    if (MODE == 1) {
        wr0 = (lrow & 3) * 256 + bn * 32 + (lrow >> 2);
        const int c1 = lrow + 64;
        wr1 = (c1 & 3) * 256 + bn * 32 + (c1 >> 2);
    } else {
        wr0 = bn * 128 + lrow;
        wr1 = bn * 128 + lrow + 64;
    }

    unsigned long long acc[8][4];
#pragma unroll
    for (int i = 0; i < 8; ++i)
#pragma unroll
        for (int j = 0; j < 4; ++j) acc[i][j] = 0ULL;

    float4 pa0, pa1, pw0, pw1;
    pa0 = *reinterpret_cast<const float4*>(A1 + (size_t)(bm + lrow)      * lda1 + kq);
    pa1 = *reinterpret_cast<const float4*>(A1 + (size_t)(bm + lrow + 64) * lda1 + kq);
    pw0 = *reinterpret_cast<const float4*>(W1 + (size_t)wr0 * 256 + kq);
    pw1 = *reinterpret_cast<const float4*>(W1 + (size_t)wr1 * 256 + kq);

    As[0][kq + 0][lrow] = pa0.x; As[0][kq + 1][lrow] = pa0.y;
    As[0][kq + 2][lrow] = pa0.z; As[0][kq + 3][lrow] = pa0.w;
    As[0][kq + 0][lrow + 64] = pa1.x; As[0][kq + 1][lrow + 64] = pa1.y;
    As[0][kq + 2][lrow + 64] = pa1.z; As[0][kq + 3][lrow + 64] = pa1.w;
    Ws[0][kq + 0][lrow] = pw0.x; Ws[0][kq + 1][lrow] = pw0.y;
    Ws[0][kq + 2][lrow] = pw0.z; Ws[0][kq + 3][lrow] = pw0.w;
    Ws[0][kq + 0][lrow + 64] = pw1.x; Ws[0][kq + 1][lrow + 64] = pw1.y;
    Ws[0][kq + 2][lrow + 64] = pw1.z; Ws[0][kq + 3][lrow + 64] = pw1.w;
    __syncthreads();

    for (int tt = 0; tt < NT; ++tt) {
        const int cb = tt & 1;
        if (tt + 1 < NT) {
            const int ts = tt + 1;
            const float* A; const float* W; int lda, k0;
            if (MODE == 1 && ts >= 16) { A = A2; lda = 256; W = W2; k0 = (ts - 16) * 16; }
            else                       { A = A1; lda = lda1; W = W1; k0 = ts * 16; }
            pa0 = *reinterpret_cast<const float4*>(A + (size_t)(bm + lrow)      * lda + k0 + kq);
            pa1 = *reinterpret_cast<const float4*>(A + (size_t)(bm + lrow + 64) * lda + k0 + kq);
            pw0 = *reinterpret_cast<const float4*>(W + (size_t)wr0 * 256 + k0 + kq);
            pw1 = *reinterpret_cast<const float4*>(W + (size_t)wr1 * 256 + k0 + kq);
        }

#pragma unroll
        for (int k = 0; k < 16; ++k) {
            const float4 a0 = *reinterpret_cast<const float4*>(&As[cb][k][ty * 8]);
            const float4 a1 = *reinterpret_cast<const float4*>(&As[cb][k][ty * 8 + 4]);
            const ulonglong2 w01 = *reinterpret_cast<const ulonglong2*>(&Ws[cb][k][tx * 8]);
            const ulonglong2 w23 = *reinterpret_cast<const ulonglong2*>(&Ws[cb][k][tx * 8 + 4]);
            fma8(acc[0], a0.x, w01, w23);
            fma8(acc[1], a0.y, w01, w23);
            fma8(acc[2], a0.z, w01, w23);
            fma8(acc[3], a0.w, w01, w23);
            fma8(acc[4], a1.x, w01, w23);
            fma8(acc[5], a1.y, w01, w23);
            fma8(acc[6], a1.z, w01, w23);
            fma8(acc[7], a1.w, w01, w23);
        }

        if (tt + 1 < NT) {
            const int nb = cb ^ 1;
            As[nb][kq + 0][lrow] = pa0.x; As[nb][kq + 1][lrow] = pa0.y;
            As[nb][kq + 2][lrow] = pa0.z; As[nb][kq + 3][lrow] = pa0.w;
            As[nb][kq + 0][lrow + 64] = pa1.x; As[nb][kq + 1][lrow + 64] = pa1.y;
            As[nb][kq + 2][lrow + 64] = pa1.z; As[nb][kq + 3][lrow + 64] = pa1.w;
            Ws[nb][kq + 0][lrow] = pw0.x; Ws[nb][kq + 1][lrow] = pw0.y;
            Ws[nb][kq + 2][lrow] = pw0.z; Ws[nb][kq + 3][lrow] = pw0.w;
            Ws[nb][kq + 0][lrow + 64] = pw1.x; Ws[nb][kq + 1][lrow + 64] = pw1.y;
            Ws[nb][kq + 2][lrow + 64] = pw1.z; Ws[nb][kq + 3][lrow + 64] = pw1.w;
            __syncthreads();
        }
    }

    if (MODE == 1) {
        const int ebase = bn * 32 + tx * 2;
        float b0[2], b1[2], b2[2], b3[2];
#pragma unroll
        for (int ee = 0; ee < 2; ++ee) {
            b0[ee] = bih[      ebase + ee] + bhh[      ebase + ee];
            b1[ee] = bih[256 + ebase + ee] + bhh[256 + ebase + ee];
            b2[ee] = bih[512 + ebase + ee] + bhh[512 + ebase + ee];
            b3[ee] = bih[768 + ebase + ee] + bhh[768 + ebase + ee];
        }
#pragma unroll
        for (int i = 0; i < 8; ++i) {
            const int m = bm + ty * 8 + i;
            const bool act = (t < lengths[m]);
#pragma unroll
            for (int ee = 0; ee < 2; ++ee) {
                const int off = m * 256 + ebase + ee;
                if (act) {
                    float gi, gf, gg, go;
                    UNPACK2(gi, gf, acc[i][ee * 2]);
                    UNPACK2(gg, go, acc[i][ee * 2 + 1]);
                    gi += b0[ee]; gf += b1[ee]; gg += b2[ee]; go += b3[ee];
                    float c = Cs[off];
                    c = fsig(gf) * c + fsig(gi) * ftanh_(gg);
                    Cs[off] = c;
                    Hw[off] = fsig(go) * ftanh_(c);
                } else {
                    Hw[off] = Hr[off];
                }
            }
        }
    } else {
#pragma unroll
        for (int i = 0; i < 8; ++i) {
            float o[8];
            UNPACK2(o[0], o[1], acc[i][0]);
            UNPACK2(o[2], o[3], acc[i][1]);
            UNPACK2(o[4], o[5], acc[i][2]);
            UNPACK2(o[6], o[7], acc[i][3]);
            float* dst = Cmat + (size_t)(bm + ty * 8 + i) * GATES + bn * 128 + tx * 8;
            *reinterpret_cast<float4*>(dst)     = make_float4(o[0], o[1], o[2], o[3]);
            *reinterpret_cast<float4*>(dst + 4) = make_float4(o[4], o[5], o[6], o[7]);
        }
    }
}

// ---------------------------------------------------------------------------
// Serial instruction LSTM: 8-CTA cluster. R5 structure (best measured:
// ~1750cyc/step) with 16-byte st.async.v4.b32 messages: 64 messages/step
// at each receiver instead of 128. Local parity mbarrier wait; no
// barrier.cluster in the loop.
// hbuf layout: 4 chunks of 64 floats padded to 68; h element vg at float
// index (vg>>6)*68 + (vg&63); each CTA's 32 values are 128B contiguous.
// ---------------------------------------------------------------------------
__global__ void __launch_bounds__(512, 1) __cluster_dims__(NCLUS, 1, 1)
ins_lstm(const float* __restrict__ G,
         const float* __restrict__ Whh,
         const float* __restrict__ bih,
         const float* __restrict__ bhh,
         const float* __restrict__ Wl,
         float* __restrict__ part)
{
    __shared__ __align__(16) float hbuf[2][272];   // 2 x (4*68)
    __shared__ float gs[128];
    __shared__ __align__(8) unsigned long long bar2[2];

    const int tid = threadIdx.x;
    const int cta = blockIdx.x;
    const int r   = tid >> 2;            // gate row within CTA, 0..127
    const int q   = tid & 3;             // 64-wide k chunk
    const int grow = (r >> 5) * 256 + cta * 32 + (r & 31);

    // pack this thread's 64 weights as 32 f32x2 pairs
    unsigned long long w2[32];
#pragma unroll
    for (int jj = 0; jj < 16; ++jj) {
        const float4 v = *reinterpret_cast<const float4*>(
            Whh + (size_t)grow * 256 + q * 64 + jj * 4);
        asm("mov.b64 %0, {%1, %2};" : "=l"(w2[2 * jj])
            : "r"(__float_as_uint(v.x)), "r"(__float_as_uint(v.y)));
        asm("mov.b64 %0, {%1, %2};" : "=l"(w2[2 * jj + 1])
            : "r"(__float_as_uint(v.z)), "r"(__float_as_uint(v.w)));
    }
    const float brow = bih[grow] + bhh[grow];
    const float wl = (tid < 32) ? Wl[cta * 32 + tid] : 0.0f;
    float cst = 0.0f;

    for (int i = tid; i < 2 * 272; i += 512)
        (&hbuf[0][0])[i] = 0.0f;

    const uint32_t hbase = (uint32_t)__cvta_generic_to_shared(&hbuf[0][0]);
    const uint32_t bbase = (uint32_t)__cvta_generic_to_shared(&bar2[0]);

    // init + pre-arm both barriers (count=1; expect 8 CTAs * 128B = 1024B)
    if (tid == 0) {
        asm volatile("mbarrier.init.shared.b64 [%0], 1;" :: "r"(bbase) : "memory");
        asm volatile("mbarrier.init.shared.b64 [%0], 1;" :: "r"(bbase + 8) : "memory");
        asm volatile("mbarrier.arrive.expect_tx.shared.b64 _, [%0], 1024;"
                     :: "r"(bbase) : "memory");
        asm volatile("mbarrier.arrive.expect_tx.shared.b64 _, [%0], 1024;"
                     :: "r"(bbase + 8) : "memory");
    }

    // remote addresses (warp0 lanes 0..7): for peer j, this lane's 16B slice
    // of this CTA's 128B chunk in peer j's hbuf (buffer 0).
    uint32_t rh[NCLUS];
    uint32_t rb[NCLUS];
    {
        const uint32_t coff = (uint32_t)(((cta >> 1) * 68 + (cta & 1) * 32) * 4
                                         + (tid & 7) * 16);
#pragma unroll
        for (int j = 0; j < NCLUS; ++j) {
            uint32_t a, b;
            asm("mapa.shared::cluster.u32 %0, %1, %2;" : "=r"(a) : "r"(hbase), "r"(j));
            asm("mapa.shared::cluster.u32 %0, %1, %2;" : "=r"(b) : "r"(bbase), "r"(j));
            rh[j] = a + coff;
            rb[j] = b;
        }
    }

    __syncthreads();
    asm volatile("barrier.cluster.arrive.aligned;" ::: "memory");
    asm volatile("barrier.cluster.wait.aligned;" ::: "memory");

    float gp0 = 0.0f, gp1 = 0.0f;
    if (q == 0) {
        gp0 = __ldg(&G[grow]);
        gp1 = __ldg(&G[GATES + grow]);
    }

    int php0 = 0, php1 = 0;   // parity trackers for bar2[0], bar2[1]
    for (int s = 0; s < N_INS; ++s) {
        const int p = s & 1;

        if (s > 0) {
            // wait for this step's h (local, cheap) + re-arm for step s+2
            const uint32_t ba = bbase + (uint32_t)(p * 8);
            const int ph = p ? php1 : php0;
            asm volatile(
                "{\n\t.reg .pred P;\n"
                "WL%=:\n\t"
                "mbarrier.try_wait.parity.acquire.cta.shared::cta.b64 P, [%0], %1, 0x989680;\n\t"
                "@!P bra WL%=;\n\t}"
                :: "r"(ba), "r"(ph) : "memory");
            if (p) php1 ^= 1; else php0 ^= 1;
            if (tid == 0)
                asm volatile("mbarrier.arrive.expect_tx.shared.b64 _, [%0], 1024;"
                             :: "r"(ba) : "memory");
        }

        // prefetch x-part of gates 2 steps ahead
        float gn = 0.0f;
        if (q == 0) {
            const int sn = (s + 2 < N_INS) ? s + 2 : N_INS - 1;
            gn = __ldg(&G[(size_t)sn * GATES + grow]);
        }

        // packed dot over this thread's 64-chunk of h
        const ulonglong2* hp = reinterpret_cast<const ulonglong2*>(&hbuf[p][q * 68]);
        unsigned long long a2 = 0ULL, b2 = 0ULL;
#pragma unroll
        for (int jj = 0; jj < 16; ++jj) {
            const ulonglong2 hv = hp[jj];
            FMA2(a2, w2[2 * jj],     hv.x);
            FMA2(b2, w2[2 * jj + 1], hv.y);
        }
        float s0, s1, s2, s3;
        UNPACK2(s0, s1, a2);
        UNPACK2(s2, s3, b2);
        float acc = (s0 + s1) + (s2 + s3);
        acc += __shfl_xor_sync(0xffffffffu, acc, 1);
        acc += __shfl_xor_sync(0xffffffffu, acc, 2);
        if (q == 0) gs[r] = acc + gp0 + brow;
        gp0 = gp1; gp1 = gn;
        __syncthreads();                     // gs ready (all hbuf[p] reads done)

        if (tid < 32) {
            const float gi = gs[tid];
            const float gf = gs[32 + tid];
            const float gg = gs[64 + tid];
            const float go = gs[96 + tid];
            cst = fsig(gf) * cst + fsig(gi) * ftanh_(gg);
            const float h = fsig(go) * ftanh_(cst);

            // gather 4 consecutive h values for this lane's 16B slice
            const int cb4 = (tid & 7) * 4;
            const float v0 = __shfl_sync(0xffffffffu, h, cb4);
            const float v1 = __shfl_sync(0xffffffffu, h, cb4 + 1);
            const float v2 = __shfl_sync(0xffffffffu, h, cb4 + 2);
            const float v3 = __shfl_sync(0xffffffffu, h, cb4 + 3);

            if (tid < 8 && s + 1 < N_INS) {
                const uint32_t bufo = (uint32_t)((p ^ 1) * 272 * 4);
                const uint32_t baro = (uint32_t)((p ^ 1) * 8);
                // destination-rotated: lane l hits peer (l+k)&7 at slot k
#pragma unroll
                for (int k = 0; k < NCLUS; ++k) {
                    const int jp = (tid + k) & 7;
                    asm volatile(
                        "st.async.shared::cluster.mbarrier::complete_tx::bytes.v4.b32 "
                        "[%0], {%1, %2, %3, %4}, [%5];"
                        :: "r"(rh[jp] + bufo),
                           "r"(__float_as_uint(v0)), "r"(__float_as_uint(v1)),
                           "r"(__float_as_uint(v2)), "r"(__float_as_uint(v3)),
                           "r"(rb[jp] + baro)
                        : "memory");
                }
            }

            // output projection (off the sync path)
            float pp = h * wl;
#pragma unroll
            for (int o = 16; o > 0; o >>= 1)
                pp += __shfl_xor_sync(0xffffffffu, pp, o);
            if (tid == 0) part[(size_t)cta * N_INS + s] = pp;
        }
    }
}

// ---------------------------------------------------------------------------
__global__ void __launch_bounds__(256)
finalize(float* __restrict__ out, const float* __restrict__ part,
         const float* __restrict__ bl)
{
    const int n = blockIdx.x * 256 + threadIdx.x;
    float s = bl[0];
#pragma unroll
    for (int k = 0; k < NCLUS; ++k) s += part[(size_t)k * N_INS + n];
    out[n] = s;
}

// ---------------------------------------------------------------------------
extern "C" void kernel_launch(void* const* d_in, const int* in_sizes, int n_in,
                              void* d_out, int out_size)
{
    const float* tokens = (const float*)d_in[0];
    const int*   lengths= (const int*)  d_in[1];
    const float* Wih_t  = (const float*)d_in[2];
    const float* Whh_t  = (const float*)d_in[3];
    const float* bih_t  = (const float*)d_in[4];
    const float* bhh_t  = (const float*)d_in[5];
    const float* Wih_i  = (const float*)d_in[6];
    const float* Whh_i  = (const float*)d_in[7];
    const float* bih_i  = (const float*)d_in[8];
    const float* bhh_i  = (const float*)d_in[9];
    const float* Wl     = (const float*)d_in[10];
    const float* bl     = (const float*)d_in[11];
    float* out = (float*)d_out;

    float *H, *C, *G, *part;
    cudaGetSymbolAddress((void**)&H,    g_H);
    cudaGetSymbolAddress((void**)&C,    g_C);
    cudaGetSymbolAddress((void**)&G,    g_G);
    cudaGetSymbolAddress((void**)&part, g_part);

    cudaMemsetAsync(H, 0, (size_t)2 * N_INS * HID * sizeof(float));
    cudaMemsetAsync(C, 0, (size_t)N_INS * HID * sizeof(float));

    const size_t NH = (size_t)N_INS * HID;
    dim3 grid(N_INS / 128, 8);

    // ---- token-level LSTM: 16 fused GEMM+pointwise steps (H ping-pong) ----
    for (int t = 0; t < T_MAX; ++t) {
        float* hr = H + (size_t)(t & 1) * NH;
        float* hw = H + (size_t)((t & 1) ^ 1) * NH;
        gemm_k<1><<<grid, 256>>>(nullptr,
                                 tokens + (size_t)t * HID, T_MAX * HID, Wih_t,
                                 hr, Whh_t,
                                 lengths, bih_t, bhh_t,
                                 hr, hw, C, t);
    }

    // ---- precompute ins_embeds @ Wih_i^T into G ----
    gemm_k<0><<<grid, 256>>>(G, H, HID, Wih_i,
                             nullptr, nullptr, nullptr, nullptr, nullptr,
                             nullptr, nullptr, nullptr, 0);

    // ---- serial instruction-level LSTM (8-CTA cluster, v4 st.async) ----
    ins_lstm<<<NCLUS, 512>>>(G, Whh_i, bih_i, bhh_i, Wl, part);

    // ---- output projection finalize ----
    finalize<<<N_INS / 256, 256>>>(out, part, bl);
}

// round 12
// speedup vs baseline: 1.2519x; 1.2519x over previous
#include <cuda_runtime.h>
#include <cuda_bf16.h>
#include <cstdint>

#define N_INS 8192
#define T_MAX 16
#define HID   256
#define GATES 1024
#define NCLUS 8

__device__ unsigned short g_Tbh[N_INS * T_MAX * HID];
__device__ unsigned short g_Tbl[N_INS * T_MAX * HID];
__device__ unsigned short g_W0h[GATES * HID], g_W0l[GATES * HID];   // Wih_t
__device__ unsigned short g_W1h[GATES * HID], g_W1l[GATES * HID];   // Whh_t
__device__ unsigned short g_W2h[GATES * HID], g_W2l[GATES * HID];   // Wih_i
__device__ unsigned short g_Hh[2][N_INS * HID], g_Hl[2][N_INS * HID];
__device__ float g_C[N_INS * HID];
__device__ float g_G[N_INS * GATES];
__device__ float g_part[NCLUS * N_INS];

#define FMA2(d, a, b) \
    asm("fma.rn.f32x2 %0, %1, %2, %0;" : "+l"(d) : "l"(a), "l"(b))
#define UNPACK2(lo, hi, v) \
    asm("mov.b64 {%0, %1}, %2;" : "=f"(lo), "=f"(hi) : "l"(v))
#define MBAR_WAIT(addr, ph)                                                     \
    asm volatile("{\n\t.reg .pred P;\nWL%=:\n\t"                                \
        "mbarrier.try_wait.parity.acquire.cta.shared::cta.b64 P, [%0], %1, 0x989680;\n\t" \
        "@!P bra WL%=;\n\t}" :: "r"(addr), "r"(ph) : "memory")

__device__ __forceinline__ float fsig(float x) {
    return __fdividef(1.0f, 1.0f + __expf(-x));
}
__device__ __forceinline__ float ftanh_(float x) {
    float e2 = __expf(2.0f * fminf(x, 30.0f));
    return __fdividef(e2 - 1.0f, e2 + 1.0f);
}

// ---- fp32 -> bf16 hi/lo ----
__global__ void __launch_bounds__(256)
conv_pair(const float* __restrict__ in, unsigned short* __restrict__ hi,
          unsigned short* __restrict__ lo, int n4)
{
    int i = blockIdx.x * 256 + threadIdx.x;
    if (i >= n4) return;
    float4 v = reinterpret_cast<const float4*>(in)[i];
    ushort4 h, l;
    float* vp = &v.x;
    unsigned short* hp = &h.x;
    unsigned short* lp = &l.x;
#pragma unroll
    for (int k = 0; k < 4; ++k) {
        __nv_bfloat16 b = __float2bfloat16_rn(vp[k]);
        hp[k] = __bfloat16_as_ushort(b);
        lp[k] = __bfloat16_as_ushort(__float2bfloat16_rn(vp[k] - __bfloat162float(b)));
    }
    reinterpret_cast<ushort4*>(hi)[i] = h;
    reinterpret_cast<ushort4*>(lo)[i] = l;
}

// ---- HMMA primitives (baseline PTX, valid on plain sm_103) ----
__device__ __forceinline__ void ldsm4(uint32_t& r0, uint32_t& r1,
                                      uint32_t& r2, uint32_t& r3, uint32_t addr) {
    asm volatile("ldmatrix.sync.aligned.m8n8.x4.shared.b16 {%0,%1,%2,%3}, [%4];"
                 : "=r"(r0), "=r"(r1), "=r"(r2), "=r"(r3) : "r"(addr));
}
__device__ __forceinline__ void mma16816(float* d, const uint32_t* a,
                                         uint32_t b0, uint32_t b1) {
    asm volatile(
        "mma.sync.aligned.m16n8k16.row.col.f32.bf16.bf16.f32 "
        "{%0,%1,%2,%3}, {%4,%5,%6,%7}, {%8,%9}, {%0,%1,%2,%3};"
        : "+f"(d[0]), "+f"(d[1]), "+f"(d[2]), "+f"(d[3])
        : "r"(a[0]), "r"(a[1]), "r"(a[2]), "r"(a[3]), "r"(b0), "r"(b1));
}

// smem tile pitch: 72 bf16 = 144 B = 36 words -> ldmatrix phases conflict-free
#define PITCH   144
#define A_BYTES (128 * PITCH)
#define SMEM_SZ (2 * A_BYTES)   // 36864

// ---------------------------------------------------------------------------
// HMMA bf16x3 GEMM. CTA tile 128(M) x 128(N), 8 warps (4 M x 2 N),
// warp tile 32x64 = 2 m16 x 8 n8 frags. K streamed in 64-bf16 chunks.
// MODE 1: [tok_t|H]@[Wih_t|Whh_t]^T (3 passes, 24 chunks) + fused LSTM
//         epilogue. Column mapping: col c -> W row (c&3)*256 + bn*32 + (c>>2)
//         (i.e. col = 4*e_local + gate).
// MODE 0: H@Wih_i^T (3 passes, 12 chunks) -> G, plain cols bn*128 + c.
// ---------------------------------------------------------------------------
template<int MODE>
__global__ void __launch_bounds__(256, 2)
gemm_mma(const unsigned short* __restrict__ Ath, const unsigned short* __restrict__ Atl,
         const unsigned short* __restrict__ Hh,  const unsigned short* __restrict__ Hl,
         const unsigned short* __restrict__ W0h, const unsigned short* __restrict__ W0l,
         const unsigned short* __restrict__ W1h, const unsigned short* __restrict__ W1l,
         const int* __restrict__ lengths,
         const float* __restrict__ bih, const float* __restrict__ bhh,
         unsigned short* __restrict__ Hwh, unsigned short* __restrict__ Hwl,
         float* __restrict__ Cs, float* __restrict__ Gout, int t)
{
    extern __shared__ __align__(16) char sm[];
    __shared__ __align__(16) float bs[128];

    const int tid  = threadIdx.x;
    const int wid  = tid >> 5;
    const int lane = tid & 31;
    const int bm   = blockIdx.x * 128;
    const int bn   = blockIdx.y;
    const int wM   = (wid & 3) * 32;
    const int wN   = (wid >> 2) * 64;
    const int NC   = (MODE == 1) ? 24 : 12;

    const uint32_t smA = (uint32_t)__cvta_generic_to_shared(sm);
    const uint32_t smB = smA + A_BYTES;

    if (MODE == 1 && tid < 128) {
        const int wr = (tid & 3) * 256 + bn * 32 + (tid >> 2);
        bs[tid] = bih[wr] + bhh[wr];
    }

    float acc[2][8][4];
#pragma unroll
    for (int i = 0; i < 2; ++i)
#pragma unroll
        for (int j = 0; j < 8; ++j)
#pragma unroll
            for (int k = 0; k < 4; ++k) acc[i][j][k] = 0.0f;

    // per-lane ldmatrix offsets (within-tile, bytes)
    const uint32_t aoff = (uint32_t)((lane & 15) * PITCH + ((lane >> 4) << 4));
    const uint32_t boff = (uint32_t)(((lane & 7) + ((lane >> 4) << 3)) * PITCH
                                     + (((lane >> 3) & 1) << 4));

    for (int c = 0; c < NC; ++c) {
        // resolve chunk sources
        const unsigned short *Ap, *Wp;
        size_t strA;
        int kk;
        if (MODE == 1) {
            const int pass = c >> 3, cc = c & 7;
            kk = (cc & 3) * 64;
            if (cc < 4) { Ap = (pass < 2) ? Ath : Atl; strA = T_MAX * HID;
                          Wp = (pass == 1) ? W0l : W0h; }
            else        { Ap = (pass < 2) ? Hh : Hl;   strA = HID;
                          Wp = (pass == 1) ? W1l : W1h; }
        } else {
            const int pass = c >> 2;
            kk = (c & 3) * 64;
            Ap = (pass < 2) ? Hh : Hl; strA = HID;
            Wp = (pass == 1) ? W0l : W0h;
        }

        // load A and B tiles: 128 rows x 64 bf16, pitch 144B
#pragma unroll
        for (int it = 0; it < 4; ++it) {
            const int u = tid + it * 256;          // 0..1023
            const int r = u >> 3, k8 = u & 7;
            *reinterpret_cast<uint4*>(sm + r * PITCH + k8 * 16) =
                *reinterpret_cast<const uint4*>(Ap + (size_t)(bm + r) * strA + kk + k8 * 8);
            const int wr = (MODE == 1) ? ((r & 3) * 256 + bn * 32 + (r >> 2))
                                       : (bn * 128 + r);
            *reinterpret_cast<uint4*>(sm + A_BYTES + r * PITCH + k8 * 16) =
                *reinterpret_cast<const uint4*>(Wp + (size_t)wr * HID + kk + k8 * 8);
        }
        __syncthreads();

#pragma unroll
        for (int g = 0; g < 4; ++g) {
            uint32_t a[2][4];
#pragma unroll
            for (int mt = 0; mt < 2; ++mt)
                ldsm4(a[mt][0], a[mt][1], a[mt][2], a[mt][3],
                      smA + (uint32_t)((wM + mt * 16) * PITCH) + aoff + 32 * g);
#pragma unroll
            for (int np = 0; np < 4; ++np) {
                uint32_t b0, b1, b2, b3;
                ldsm4(b0, b1, b2, b3,
                      smB + (uint32_t)((wN + np * 16) * PITCH) + boff + 32 * g);
#pragma unroll
                for (int mt = 0; mt < 2; ++mt) {
                    mma16816(acc[mt][np * 2],     a[mt], b0, b1);
                    mma16816(acc[mt][np * 2 + 1], a[mt], b2, b3);
                }
            }
        }
        __syncthreads();
    }

    if (MODE == 1) {
        const bool odd = (lane & 1);
        const int er   = lane >> 2;            // 0..7
        const int esub = (lane >> 1) & 1;      // element within n-tile pair
#pragma unroll
        for (int mt = 0; mt < 2; ++mt) {
            const int m = bm + wM + mt * 16 + er + (odd ? 8 : 0);
            const bool act = (t < lengths[m]);
#pragma unroll
            for (int nt = 0; nt < 8; ++nt) {
                float c0 = acc[mt][nt][0], c1 = acc[mt][nt][1];
                float c2 = acc[mt][nt][2], c3 = acc[mt][nt][3];
                // lane-pair exchange: even lane keeps row r (needs g,o from odd);
                // odd lane keeps row r+8 (needs i,f from even)
                const float x0 = __shfl_xor_sync(0xffffffffu, c0, 1);
                const float x1 = __shfl_xor_sync(0xffffffffu, c1, 1);
                const float x2 = __shfl_xor_sync(0xffffffffu, c2, 1);
                const float x3 = __shfl_xor_sync(0xffffffffu, c3, 1);
                const float gi = odd ? x2 : c0;
                const float gf = odd ? x3 : c1;
                const float gg = odd ? c2 : x0;
                const float go = odd ? c3 : x1;

                const int e_local = (wid >> 2) * 16 + nt * 2 + esub;
                const size_t off = (size_t)m * 256 + bn * 32 + e_local;
                if (act) {
                    const float4 bb = *reinterpret_cast<const float4*>(&bs[4 * e_local]);
                    float cc = Cs[off];
                    cc = fsig(gf + bb.y) * cc + fsig(gi + bb.x) * ftanh_(gg + bb.z);
                    Cs[off] = cc;
                    const float h = fsig(go + bb.w) * ftanh_(cc);
                    const __nv_bfloat16 bh = __float2bfloat16_rn(h);
                    Hwh[off] = __bfloat16_as_ushort(bh);
                    Hwl[off] = __bfloat16_as_ushort(
                        __float2bfloat16_rn(h - __bfloat162float(bh)));
                } else {
                    Hwh[off] = Hh[off];
                    Hwl[off] = Hl[off];
                }
            }
        }
    } else {
        const int er = lane >> 2;
        const int cb = 2 * (lane & 3);
#pragma unroll
        for (int mt = 0; mt < 2; ++mt) {
            const int m = bm + wM + mt * 16 + er;
#pragma unroll
            for (int nt = 0; nt < 8; ++nt) {
                const int col = bn * 128 + wN + nt * 8 + cb;
                *reinterpret_cast<float2*>(Gout + (size_t)m * GATES + col) =
                    make_float2(acc[mt][nt][0], acc[mt][nt][1]);
                *reinterpret_cast<float2*>(Gout + (size_t)(m + 8) * GATES + col) =
                    make_float2(acc[mt][nt][2], acc[mt][nt][3]);
            }
        }
    }
}

// ---------------------------------------------------------------------------
// Serial instruction LSTM — Round-5 structure verbatim (best: ~1750 cyc/step).
// ---------------------------------------------------------------------------
__global__ void __launch_bounds__(512, 1) __cluster_dims__(NCLUS, 1, 1)
ins_lstm(const float* __restrict__ G,
         const float* __restrict__ Whh,
         const float* __restrict__ bih,
         const float* __restrict__ bhh,
         const float* __restrict__ Wl,
         float* __restrict__ part)
{
    __shared__ __align__(16) float hbuf[2][272];
    __shared__ float gs[128];
    __shared__ __align__(8) unsigned long long bar2[2];

    const int tid = threadIdx.x;
    const int cta = blockIdx.x;
    const int r   = tid >> 2;
    const int q   = tid & 3;
    const int grow = (r >> 5) * 256 + cta * 32 + (r & 31);

    unsigned long long w2[32];
#pragma unroll
    for (int jj = 0; jj < 16; ++jj) {
        const float4 v = *reinterpret_cast<const float4*>(
            Whh + (size_t)grow * 256 + q * 64 + jj * 4);
        asm("mov.b64 %0, {%1, %2};" : "=l"(w2[2 * jj])
            : "r"(__float_as_uint(v.x)), "r"(__float_as_uint(v.y)));
        asm("mov.b64 %0, {%1, %2};" : "=l"(w2[2 * jj + 1])
            : "r"(__float_as_uint(v.z)), "r"(__float_as_uint(v.w)));
    }
    const float brow = bih[grow] + bhh[grow];
    const float wl = (tid < 32) ? Wl[cta * 32 + tid] : 0.0f;
    float cst = 0.0f;

    for (int i = tid; i < 2 * 272; i += 512)
        (&hbuf[0][0])[i] = 0.0f;

    const uint32_t hbase = (uint32_t)__cvta_generic_to_shared(&hbuf[0][0]);
    const uint32_t bbase = (uint32_t)__cvta_generic_to_shared(&bar2[0]);

    if (tid == 0) {
        asm volatile("mbarrier.init.shared.b64 [%0], 1;" :: "r"(bbase) : "memory");
        asm volatile("mbarrier.init.shared.b64 [%0], 1;" :: "r"(bbase + 8) : "memory");
        asm volatile("mbarrier.arrive.expect_tx.shared.b64 _, [%0], 1024;"
                     :: "r"(bbase) : "memory");
        asm volatile("mbarrier.arrive.expect_tx.shared.b64 _, [%0], 1024;"
                     :: "r"(bbase + 8) : "memory");
    }

    uint32_t rh[NCLUS], rb[NCLUS];
    {
        const uint32_t coff = (uint32_t)(((cta >> 1) * 68 + (cta & 1) * 32) * 4
                                         + (tid & 15) * 8);
#pragma unroll
        for (int j = 0; j < NCLUS; ++j) {
            uint32_t a, b;
            asm("mapa.shared::cluster.u32 %0, %1, %2;" : "=r"(a) : "r"(hbase), "r"(j));
            asm("mapa.shared::cluster.u32 %0, %1, %2;" : "=r"(b) : "r"(bbase), "r"(j));
            rh[j] = a + coff;
            rb[j] = b;
        }
    }

    __syncthreads();
    asm volatile("barrier.cluster.arrive.aligned;" ::: "memory");
    asm volatile("barrier.cluster.wait.aligned;" ::: "memory");

    float gp0 = 0.0f, gp1 = 0.0f;
    if (q == 0) {
        gp0 = __ldg(&G[grow]);
        gp1 = __ldg(&G[GATES + grow]);
    }

    int php0 = 0, php1 = 0;
    for (int s = 0; s < N_INS; ++s) {
        const int p = s & 1;

        if (s > 0) {
            const uint32_t ba = bbase + (uint32_t)(p * 8);
            const int phx = p ? php1 : php0;
            MBAR_WAIT(ba, phx);
            if (p) php1 ^= 1; else php0 ^= 1;
            if (tid == 0)
                asm volatile("mbarrier.arrive.expect_tx.shared.b64 _, [%0], 1024;"
                             :: "r"(ba) : "memory");
        }

        float gn = 0.0f;
        if (q == 0) {
            const int sn = (s + 2 < N_INS) ? s + 2 : N_INS - 1;
            gn = __ldg(&G[(size_t)sn * GATES + grow]);
        }

        const ulonglong2* hp = reinterpret_cast<const ulonglong2*>(&hbuf[p][q * 68]);
        unsigned long long a2 = 0ULL, b2 = 0ULL;
#pragma unroll
        for (int jj = 0; jj < 16; ++jj) {
            const ulonglong2 hv = hp[jj];
            FMA2(a2, w2[2 * jj],     hv.x);
            FMA2(b2, w2[2 * jj + 1], hv.y);
        }
        float s0, s1, s2, s3;
        UNPACK2(s0, s1, a2);
        UNPACK2(s2, s3, b2);
        float acc = (s0 + s1) + (s2 + s3);
        acc += __shfl_xor_sync(0xffffffffu, acc, 1);
        acc += __shfl_xor_sync(0xffffffffu, acc, 2);
        if (q == 0) gs[r] = acc + gp0 + brow;
        gp0 = gp1; gp1 = gn;
        __syncthreads();

        if (tid < 32) {
            const float gi = gs[tid];
            const float gf = gs[32 + tid];
            const float gg = gs[64 + tid];
            const float go = gs[96 + tid];
            cst = fsig(gf) * cst + fsig(gi) * ftanh_(gg);
            const float h = fsig(go) * ftanh_(cst);

            const float hlo = __shfl_sync(0xffffffffu, h, (tid & 15) * 2);
            const float hhi = __shfl_sync(0xffffffffu, h, (tid & 15) * 2 + 1);
            if (tid < 16 && s + 1 < N_INS) {
                unsigned long long pkt;
                asm("mov.b64 %0, {%1, %2};" : "=l"(pkt)
                    : "r"(__float_as_uint(hlo)), "r"(__float_as_uint(hhi)));
                const uint32_t bufo = (uint32_t)((p ^ 1) * 272 * 4);
                const uint32_t baro = (uint32_t)((p ^ 1) * 8);
#pragma unroll
                for (int j = 0; j < NCLUS; ++j) {
                    asm volatile(
                        "st.async.shared::cluster.mbarrier::complete_tx::bytes.b64 "
                        "[%0], %1, [%2];"
                        :: "r"(rh[j] + bufo), "l"(pkt), "r"(rb[j] + baro)
                        : "memory");
                }
            }

            float pp = h * wl;
#pragma unroll
            for (int o = 16; o > 0; o >>= 1)
                pp += __shfl_xor_sync(0xffffffffu, pp, o);
            if (tid == 0) part[(size_t)cta * N_INS + s] = pp;
        }
    }
}

__global__ void __launch_bounds__(256)
finalize(float* __restrict__ out, const float* __restrict__ part,
         const float* __restrict__ bl)
{
    const int n = blockIdx.x * 256 + threadIdx.x;
    float s = bl[0];
#pragma unroll
    for (int k = 0; k < NCLUS; ++k) s += part[(size_t)k * N_INS + n];
    out[n] = s;
}

extern "C" void kernel_launch(void* const* d_in, const int* in_sizes, int n_in,
                              void* d_out, int out_size)
{
    const float* tokens = (const float*)d_in[0];
    const int*   lengths= (const int*)  d_in[1];
    const float* Wih_t  = (const float*)d_in[2];
    const float* Whh_t  = (const float*)d_in[3];
    const float* bih_t  = (const float*)d_in[4];
    const float* bhh_t  = (const float*)d_in[5];
    const float* Wih_i  = (const float*)d_in[6];
    const float* Whh_i  = (const float*)d_in[7];
    const float* bih_i  = (const float*)d_in[8];
    const float* bhh_i  = (const float*)d_in[9];
    const float* Wl     = (const float*)d_in[10];
    const float* bl     = (const float*)d_in[11];
    float* out = (float*)d_out;

    unsigned short *Tbh, *Tbl, *W0h, *W0l, *W1h, *W1l, *W2h, *W2l, *Hh, *Hl;
    float *C, *G, *part;
    cudaGetSymbolAddress((void**)&Tbh, g_Tbh);
    cudaGetSymbolAddress((void**)&Tbl, g_Tbl);
    cudaGetSymbolAddress((void**)&W0h, g_W0h);
    cudaGetSymbolAddress((void**)&W0l, g_W0l);
    cudaGetSymbolAddress((void**)&W1h, g_W1h);
    cudaGetSymbolAddress((void**)&W1l, g_W1l);
    cudaGetSymbolAddress((void**)&W2h, g_W2h);
    cudaGetSymbolAddress((void**)&W2l, g_W2l);
    cudaGetSymbolAddress((void**)&Hh,  g_Hh);
    cudaGetSymbolAddress((void**)&Hl,  g_Hl);
    cudaGetSymbolAddress((void**)&C,   g_C);
    cudaGetSymbolAddress((void**)&G,   g_G);
    cudaGetSymbolAddress((void**)&part, g_part);

    const size_t NH = (size_t)N_INS * HID;
    cudaMemsetAsync(C, 0, NH * sizeof(float));
    cudaMemsetAsync(Hh, 0, NH * sizeof(unsigned short));
    cudaMemsetAsync(Hl, 0, NH * sizeof(unsigned short));

    conv_pair<<<(N_INS * T_MAX * HID / 4 + 255) / 256, 256>>>(
        tokens, Tbh, Tbl, N_INS * T_MAX * HID / 4);
    conv_pair<<<(GATES * HID / 4 + 255) / 256, 256>>>(Wih_t, W0h, W0l, GATES * HID / 4);
    conv_pair<<<(GATES * HID / 4 + 255) / 256, 256>>>(Whh_t, W1h, W1l, GATES * HID / 4);
    conv_pair<<<(GATES * HID / 4 + 255) / 256, 256>>>(Wih_i, W2h, W2l, GATES * HID / 4);

    dim3 grid(N_INS / 128, 8);

    for (int t = 0; t < T_MAX; ++t) {
        unsigned short* hrh = Hh + (size_t)(t & 1) * NH;
        unsigned short* hrl = Hl + (size_t)(t & 1) * NH;
        unsigned short* hwh = Hh + (size_t)((t & 1) ^ 1) * NH;
        unsigned short* hwl = Hl + (size_t)((t & 1) ^ 1) * NH;
        gemm_mma<1><<<grid, 256, SMEM_SZ>>>(Tbh + (size_t)t * HID, Tbl + (size_t)t * HID,
                                            hrh, hrl, W0h, W0l, W1h, W1l,
                                            lengths, bih_t, bhh_t,
                                            hwh, hwl, C, nullptr, t);
    }
    // final H in buffer 0
    gemm_mma<0><<<grid, 256, SMEM_SZ>>>(nullptr, nullptr, Hh, Hl,
                                        W2h, W2l, nullptr, nullptr,
                                        nullptr, nullptr, nullptr,
                                        nullptr, nullptr, nullptr, G, 0);

    ins_lstm<<<NCLUS, 512>>>(G, Whh_i, bih_i, bhh_i, Wl, part);
    finalize<<<N_INS / 256, 256>>>(out, part, bl);
}